// round 12
// baseline (speedup 1.0000x reference)
#include <cuda_runtime.h>
#include <cstdint>

// Degenerate BiLSTM: h=c=0 => only emb[:,S-1] (fwd) and emb[:,0] (bwd) matter;
// f-gate dead; Whf/Whb unused.  B=128, S=2048, EMB=128, HID=256, OUT=32.
//
// Grid 80 x 512 threads = 64 workers (16 h-chunks x 4 batch-groups) + 16 heads.
// Worker: 16 warps = (dir x 8 h-pairs); W tile (96 rows, 48KB) via 6x8KB
// cp.async.bulk; x gathered 4-threads-per-row into 132-word padded rows;
// per-warp GEMV identical to the proven R10 core (1 CF x LDS.128 + 6 broadcast
// W LDS.128 + 12 fma.rn.f32x2 per k4); dirs combined in smem; g_hy[h][b].
// Head: two independent 4-batch R10-style heads per block (halves by tid>>8),
// shared Why_s staging during the worker phase + shared epoch-safe bg poll.

#define NB_B   128
#define NB_S   2048
#define NB_EMB 128
#define NB_HID 256
#define NB_OUT 32

__device__ unsigned int g_wcnt[4];            // +16 per launch per bg (workers)
__device__ unsigned int g_hcnt[4];            // +4  per launch per bg (heads)
__device__ float        g_hy[NB_HID * NB_B];  // [h][b]

// dynamic smem byte offsets (worker / head overlays)
#define SM_XS    0              // worker: xs 8448 fl (33792 B) | head: Why_s 8320 fl
#define SM_WSM   33792          // worker: W 49152 B | head: hy_s 2*4*260 fl + red2
#define SM_RED   82944          // worker: 16*33 floats (2112 B)
#define SM_MBAR  85056          // 8 B
#define SMEM_BYTES 85088
// head sub-offsets inside SM_WSM region
#define SMH_HYS  SM_WSM         // hy_s: half*4160 + bl*1040 + k*4
#define SMH_RED2 (SM_WSM + 8320)// red2: half*528 + (bl*33+o)*4

__device__ __forceinline__ float fsigm(float x) {
    return __fdividef(1.0f, 1.0f + __expf(-x));
}
__device__ __forceinline__ float ftanh(float x) {
    float r; asm("tanh.approx.f32 %0, %1;" : "=f"(r) : "f"(x)); return r;
}
__device__ __forceinline__ unsigned int smem_u32(const void* p) {
    unsigned int a;
    asm("{ .reg .u64 t; cvta.to.shared.u64 t, %1; cvt.u32.u64 %0, t; }"
        : "=r"(a) : "l"(p));
    return a;
}
__device__ __forceinline__ unsigned long long fma2(
    unsigned long long a, unsigned long long b, unsigned long long c) {
    unsigned long long d;
    asm("fma.rn.f32x2 %0, %1, %2, %3;" : "=l"(d) : "l"(a), "l"(b), "l"(c));
    return d;
}
__device__ __forceinline__ void lds_v2b64(unsigned int a,
                                          unsigned long long& x,
                                          unsigned long long& y) {
    asm volatile("ld.shared.v2.b64 {%0, %1}, [%2];" : "=l"(x), "=l"(y) : "r"(a));
}
__device__ __forceinline__ float acc_sum(unsigned long long v) {
    return __uint_as_float((unsigned int)v) + __uint_as_float((unsigned int)(v >> 32));
}
__device__ __forceinline__ void mbar_wait0(unsigned int mbar) {
    unsigned int done;
    asm volatile(
        "{\n\t.reg .pred p;\n\t"
        "mbarrier.try_wait.parity.acquire.cta.shared::cta.b64 p, [%1], 0;\n\t"
        "selp.b32 %0, 1, 0, p;\n\t}"
        : "=r"(done) : "r"(mbar) : "memory");
    if (!done) {
        asm volatile(
            "{\n\t.reg .pred P1;\n\t"
            "WL_%=:\n\t"
            "mbarrier.try_wait.parity.acquire.cta.shared::cta.b64 P1, [%0], 0, 0x989680;\n\t"
            "@P1 bra.uni WD_%=;\n\t"
            "bra.uni WL_%=;\n\t"
            "WD_%=:\n\t}"
            :: "r"(mbar) : "memory");
    }
}

__global__ void __launch_bounds__(512, 1) bilstm_kernel(
    const int*   __restrict__ inputs,   // [B, S]
    const float* __restrict__ weight,   // [VOCAB, EMB]
    const float* __restrict__ Wxf,      // [1024, 128]
    const float* __restrict__ bxf,
    const float* __restrict__ bhf,
    const float* __restrict__ Wxb,
    const float* __restrict__ bxb,
    const float* __restrict__ bhb,
    const float* __restrict__ Why,      // [32, 256]
    const float* __restrict__ by,       // [32]
    float*       __restrict__ out)      // [B, 32]
{
    extern __shared__ char dsm[];
    const int tid = threadIdx.x;
    const int bid = blockIdx.x;

    if (bid < 64) {
        // ================= WORKER (16 h per block) =================
        const int hc     = bid >> 2;         // 0..15
        const int bg     = bid & 3;
        const int h_base = hc * 16;
        const int b_base = bg * 32;

        float* xs  = (float*)(dsm + SM_XS);    // [dir*4224 + lb*132 + e]
        float* red = (float*)(dsm + SM_RED);   // [hl*33 + lb], hl 0..15
        const unsigned int sb   = smem_u32(dsm);
        const unsigned int mbar = sb + SM_MBAR;

        // --- parallel staging ---
        if (tid < 256) {
            // 4 threads per (dir,lb) row; each copies 32 floats (8 float4).
            const int row  = tid >> 2;           // 0..63
            const int q4   = tid & 3;
            const int dir  = row >> 5;
            const int lb   = row & 31;
            const int tok  = inputs[(b_base + lb) * NB_S + (dir ? 0 : (NB_S - 1))];
            const float4* src = (const float4*)(weight + tok * NB_EMB + q4 * 32);
            float* dst = xs + dir * 4224 + lb * 132 + q4 * 32;
            #pragma unroll
            for (int e4 = 0; e4 < 8; e4++)
                *(float4*)(dst + e4 * 4) = src[e4];
        } else if (tid == 256) {
            asm volatile("mbarrier.init.shared.b64 [%0], 1;" :: "r"(mbar) : "memory");
            asm volatile("mbarrier.arrive.expect_tx.shared.b64 _, [%0], %1;"
                         :: "r"(mbar), "r"(49152u) : "memory");
            const int goff[3] = {0, 512, 768};
            #pragma unroll
            for (int c = 0; c < 6; c++) {
                const float* src = (c >= 3 ? Wxb : Wxf)
                                 + (goff[c % 3] + h_base) * NB_EMB;
                const unsigned int dst = sb + SM_WSM + c * 8192;
                asm volatile(
                    "cp.async.bulk.shared::cluster.global.mbarrier::complete_tx::bytes "
                    "[%0], [%1], %2, [%3];"
                    :: "r"(dst), "l"(src), "r"(8192u), "r"(mbar) : "memory");
            }
        }

        const int w   = tid >> 5;      // 16 warps
        const int lb  = tid & 31;      // lane = batch
        const int dir = w >> 3;        // 0 fwd / 1 bwd
        const int hp  = w & 7;         // h-pair 0..7

        // Bias sums (warp-uniform; c=0 => bx + bh only). 3 gates x 2 h.
        const float* bx = dir ? bxb : bxf;
        const float* bh = dir ? bhb : bhf;
        float bias[6];
        #pragma unroll
        for (int g = 0; g < 3; g++) {
            const int go = (g == 0 ? 0 : (g == 1 ? 512 : 768));
            #pragma unroll
            for (int j = 0; j < 2; j++) {
                const int h = h_base + 2 * hp + j;
                bias[g * 2 + j] = bx[go + h] + bh[go + h];
            }
        }

        __syncthreads();      // xs ready
        mbar_wait0(mbar);     // W tile ready

        // GEMV (R10 core): per k4: 1 x LDS.128 (CF, stride 132) + 6 broadcast
        // W LDS.128 + 12 FMA2.
        unsigned int wrow[6];
        #pragma unroll
        for (int g = 0; g < 3; g++)
            #pragma unroll
            for (int j = 0; j < 2; j++)
                wrow[g * 2 + j] = sb + SM_WSM
                                + (((dir * 3 + g) * 16) + 2 * hp + j) * 512;

        const unsigned int xaddr = sb + SM_XS + (dir * 4224 + lb * 132) * 4;

        unsigned long long acc[6] = {0ull, 0ull, 0ull, 0ull, 0ull, 0ull};
        #pragma unroll 8
        for (int k4 = 0; k4 < 32; k4++) {
            unsigned long long xa, xb;
            lds_v2b64(xaddr + k4 * 16, xa, xb);
            #pragma unroll
            for (int r = 0; r < 6; r++) {
                unsigned long long w01, w23;
                lds_v2b64(wrow[r] + k4 * 16, w01, w23);
                acc[r] = fma2(w01, xa, acc[r]);
                acc[r] = fma2(w23, xb, acc[r]);
            }
        }

        float hyv[2];
        #pragma unroll
        for (int j = 0; j < 2; j++) {
            const float gi = acc_sum(acc[0 * 2 + j]) + bias[0 * 2 + j];
            const float gg = acc_sum(acc[1 * 2 + j]) + bias[1 * 2 + j];
            const float go = acc_sum(acc[2 * 2 + j]) + bias[2 * 2 + j];
            hyv[j] = fsigm(go) * ftanh(fsigm(gi) * ftanh(gg));
        }

        // Combine dirs via smem, store hy transposed.
        __syncthreads();
        if (dir == 1) {
            red[(2 * hp + 0) * 33 + lb] = hyv[0];
            red[(2 * hp + 1) * 33 + lb] = hyv[1];
        }
        __syncthreads();
        if (dir == 0) {
            #pragma unroll
            for (int j = 0; j < 2; j++) {
                const int hl = 2 * hp + j;
                g_hy[(h_base + hl) * NB_B + b_base + lb] =
                    hyv[j] + red[hl * 33 + lb];
            }
        }

        __syncthreads();
        if (tid == 0) {
            __threadfence();
            atomicAdd(&g_wcnt[bg], 1u);
        }
    } else {
        // ========= HEAD (16 blocks; 2 independent 4-batch halves) =========
        const int hb   = bid - 64;        // 0..15
        const int bg   = hb >> 2;
        const int q    = hb & 3;
        const int half = tid >> 8;        // 0 or 1
        const int t    = tid & 255;
        const int b0   = bg * 32 + q * 8 + half * 4;

        float* Why_s = (float*)(dsm + SM_XS);                    // [o*260 + k]
        float* hy_s  = (float*)(dsm + SMH_HYS  + half * 4160);   // [bl*260 + k]
        float* red2  = (float*)(dsm + SMH_RED2 + half * 528);    // [bl*33 + o]

        // Stage Why during the worker phase (all 512 threads).
        #pragma unroll
        for (int it = 0; it < 16; it++) {
            const int idx = tid + it * 512;      // 8192
            const int o = idx >> 8;
            const int k = idx & 255;
            Why_s[o * 260 + k] = Why[idx];
        }

        // Epoch-safe wait: N = hcnt/4 (this block hasn't incremented yet);
        // wait until wcnt >= 16*(N+1).
        if (tid == 0) {
            unsigned int h0;
            asm volatile("ld.global.relaxed.gpu.u32 %0, [%1];"
                         : "=r"(h0) : "l"(&g_hcnt[bg]));
            const unsigned int target = ((h0 >> 2) + 1u) * 16u;
            unsigned int v;
            do {
                asm volatile("ld.global.acquire.gpu.u32 %0, [%1];"
                             : "=r"(v) : "l"(&g_wcnt[bg]) : "memory");
                if ((int)(v - target) >= 0) break;
                __nanosleep(32);
            } while (true);
        }
        __syncthreads();

        // Stage hy for this half's 4 batches (1024 floats).
        #pragma unroll
        for (int it = 0; it < 4; it++) {
            const int idx = t + it * 256;
            const int bl  = idx & 3;
            const int k   = idx >> 2;
            hy_s[bl * 260 + k] = g_hy[k * NB_B + b0 + bl];
        }
        __syncthreads();

        // warp = (bl, k-half); lane = output o. 32 float4-iters.
        const int o  = t & 31;
        const int w  = t >> 5;
        const int bl = w & 3;
        const int kh = w >> 2;
        const float4* hy4 = (const float4*)(hy_s + bl * 260 + kh * 128);
        const float4* wy4 = (const float4*)(Why_s + o * 260 + kh * 128);

        float a0 = 0.f, a1 = 0.f, a2 = 0.f, a3 = 0.f;
        #pragma unroll 8
        for (int k4 = 0; k4 < 32; k4++) {
            const float4 hv = hy4[k4];
            const float4 wv = wy4[k4];
            a0 = fmaf(hv.x, wv.x, a0);
            a1 = fmaf(hv.y, wv.y, a1);
            a2 = fmaf(hv.z, wv.z, a2);
            a3 = fmaf(hv.w, wv.w, a3);
        }
        const float part = (a0 + a1) + (a2 + a3);

        if (kh == 1) red2[bl * 33 + o] = part;
        __syncthreads();
        if (kh == 0) {
            const float acc = part + red2[bl * 33 + o] + by[o];
            float mx = acc;
            #pragma unroll
            for (int off = 16; off; off >>= 1)
                mx = fmaxf(mx, __shfl_xor_sync(0xffffffffu, mx, off));
            float s = __expf(acc - mx);
            #pragma unroll
            for (int off = 16; off; off >>= 1)
                s += __shfl_xor_sync(0xffffffffu, s, off);
            out[(b0 + bl) * NB_OUT + o] = acc - mx - __logf(s);
        }

        __syncthreads();
        if (tid == 0) atomicAdd(&g_hcnt[bg], 1u);
    }
}

// Inputs in metadata order:
// 0 inputs(int32) 1 weight 2 Wxf 3 bxf 4 Whf(unused) 5 bhf
// 6 Wxb 7 bxb 8 Whb(unused) 9 bhb 10 Why 11 by
extern "C" void kernel_launch(void* const* d_in, const int* in_sizes, int n_in,
                              void* d_out, int out_size)
{
    const int*   inputs = (const int*)  d_in[0];
    const float* weight = (const float*)d_in[1];
    const float* Wxf    = (const float*)d_in[2];
    const float* bxf    = (const float*)d_in[3];
    const float* bhf    = (const float*)d_in[5];
    const float* Wxb    = (const float*)d_in[6];
    const float* bxb    = (const float*)d_in[7];
    const float* bhb    = (const float*)d_in[9];
    const float* Why    = (const float*)d_in[10];
    const float* by     = (const float*)d_in[11];
    float*       out    = (float*)d_out;

    static int configured = 0;
    if (!configured) {
        cudaFuncSetAttribute(bilstm_kernel,
                             cudaFuncAttributeMaxDynamicSharedMemorySize,
                             SMEM_BYTES);
        configured = 1;
    }

    bilstm_kernel<<<80, 512, SMEM_BYTES>>>(inputs, weight, Wxf, bxf, bhf,
                                           Wxb, bxb, bhb, Why, by, out);
}

// round 13
// speedup vs baseline: 1.1372x; 1.1372x over previous
#include <cuda_runtime.h>
#include <cstdint>

// Degenerate BiLSTM: h=c=0 => only emb[:,S-1] (fwd) and emb[:,0] (bwd) matter;
// f-gate dead; Whf/Whb unused.  B=128, S=2048, EMB=128, HID=256, OUT=32.
//
// Grid 288 = 256 workers (64 h-chunks x 4 batch-groups) + 32 head blocks,
// 256 threads, smem 46.6KB -> 2 blocks/SM co-resident (phase overlap).
// Worker: warp = (dir, h) x 3 gates; W tile (24 rows, 12KB) via cp.async.bulk;
// x gathered 2-threads-per-row into 132-word padded rows (CF LDS.128);
// GEMV: per k4 1 x LDS.128 + 3 broadcast W LDS.128 + 6 fma.rn.f32x2;
// dirs combined in smem; g_hy[h][b]; fence + wcnt release.
// Head (8 per bg, 4 batches): stages Why[o][k] (260-pad) during worker phase;
// epoch-safe spin (target 64*(N+1)); vectorized float4 tail GEMV; softmax.

#define NB_B   128
#define NB_S   2048
#define NB_EMB 128
#define NB_HID 256
#define NB_OUT 32

__device__ unsigned int g_wcnt[4];            // +64 per launch per bg (workers)
__device__ unsigned int g_hcnt[4];            // +8  per launch per bg (heads)
__device__ float        g_hy[NB_HID * NB_B];  // [h][b]

// dynamic smem byte offsets (worker / head overlays)
#define SM_XS    0              // worker: xs 8448 fl (33792 B) | head: Why_s 8320 fl
#define SM_WSM   33792          // worker: W 12288 B | head: hy_s + red2
#define SM_RED   46080          // worker: 4*33 floats (528 B)
#define SM_MBAR  46608          // 8 B
#define SMEM_BYTES 46624
// head sub-offsets inside SM_WSM region
#define SMH_HYS  SM_WSM         // hy_s: bl*1040 + k*4  (4160 B)
#define SMH_RED2 (SM_WSM + 4160)// red2: (bl*33+o)*4    (528 B)

__device__ __forceinline__ float fsigm(float x) {
    return __fdividef(1.0f, 1.0f + __expf(-x));
}
__device__ __forceinline__ float ftanh(float x) {
    float r; asm("tanh.approx.f32 %0, %1;" : "=f"(r) : "f"(x)); return r;
}
__device__ __forceinline__ unsigned int smem_u32(const void* p) {
    unsigned int a;
    asm("{ .reg .u64 t; cvta.to.shared.u64 t, %1; cvt.u32.u64 %0, t; }"
        : "=r"(a) : "l"(p));
    return a;
}
__device__ __forceinline__ unsigned long long fma2(
    unsigned long long a, unsigned long long b, unsigned long long c) {
    unsigned long long d;
    asm("fma.rn.f32x2 %0, %1, %2, %3;" : "=l"(d) : "l"(a), "l"(b), "l"(c));
    return d;
}
__device__ __forceinline__ void lds_v2b64(unsigned int a,
                                          unsigned long long& x,
                                          unsigned long long& y) {
    asm volatile("ld.shared.v2.b64 {%0, %1}, [%2];" : "=l"(x), "=l"(y) : "r"(a));
}
__device__ __forceinline__ float acc_sum(unsigned long long v) {
    return __uint_as_float((unsigned int)v) + __uint_as_float((unsigned int)(v >> 32));
}
__device__ __forceinline__ void mbar_wait0(unsigned int mbar) {
    unsigned int done;
    asm volatile(
        "{\n\t.reg .pred p;\n\t"
        "mbarrier.try_wait.parity.acquire.cta.shared::cta.b64 p, [%1], 0;\n\t"
        "selp.b32 %0, 1, 0, p;\n\t}"
        : "=r"(done) : "r"(mbar) : "memory");
    if (!done) {
        asm volatile(
            "{\n\t.reg .pred P1;\n\t"
            "WL_%=:\n\t"
            "mbarrier.try_wait.parity.acquire.cta.shared::cta.b64 P1, [%0], 0, 0x989680;\n\t"
            "@P1 bra.uni WD_%=;\n\t"
            "bra.uni WL_%=;\n\t"
            "WD_%=:\n\t}"
            :: "r"(mbar) : "memory");
    }
}

__global__ void __launch_bounds__(256, 2) bilstm_kernel(
    const int*   __restrict__ inputs,   // [B, S]
    const float* __restrict__ weight,   // [VOCAB, EMB]
    const float* __restrict__ Wxf,      // [1024, 128]
    const float* __restrict__ bxf,
    const float* __restrict__ bhf,
    const float* __restrict__ Wxb,
    const float* __restrict__ bxb,
    const float* __restrict__ bhb,
    const float* __restrict__ Why,      // [32, 256]
    const float* __restrict__ by,       // [32]
    float*       __restrict__ out)      // [B, 32]
{
    extern __shared__ char dsm[];
    const int tid = threadIdx.x;
    const int bid = blockIdx.x;

    if (bid < 256) {
        // ================= WORKER (4 h per block) =================
        const int hc     = bid >> 2;         // 0..63
        const int bg     = bid & 3;
        const int h_base = hc * 4;
        const int b_base = bg * 32;

        float* xs  = (float*)(dsm + SM_XS);    // [dir*4224 + lb*132 + e]
        float* red = (float*)(dsm + SM_RED);   // [hl*33 + lb]
        const unsigned int sb   = smem_u32(dsm);
        const unsigned int mbar = sb + SM_MBAR;

        // --- parallel staging ---
        if (tid < 128) {
            // 2 threads per (dir,lb) row; each copies 64 floats (16 float4).
            const int row  = tid >> 1;
            const int half = tid & 1;
            const int dir  = row >> 5;
            const int lb   = row & 31;
            const int tok  = inputs[(b_base + lb) * NB_S + (dir ? 0 : (NB_S - 1))];
            const float4* src = (const float4*)(weight + tok * NB_EMB + half * 64);
            float* dst = xs + dir * 4224 + lb * 132 + half * 64;
            #pragma unroll
            for (int e4 = 0; e4 < 16; e4++)
                *(float4*)(dst + e4 * 4) = src[e4];
        } else if (tid == 128) {
            asm volatile("mbarrier.init.shared.b64 [%0], 1;" :: "r"(mbar) : "memory");
            asm volatile("mbarrier.arrive.expect_tx.shared.b64 _, [%0], %1;"
                         :: "r"(mbar), "r"(12288u) : "memory");
            const int goff[3] = {0, 512, 768};
            #pragma unroll
            for (int c = 0; c < 6; c++) {
                const float* src = (c >= 3 ? Wxb : Wxf)
                                 + (goff[c % 3] + h_base) * NB_EMB;
                const unsigned int dst = sb + SM_WSM + c * 2048;
                asm volatile(
                    "cp.async.bulk.shared::cluster.global.mbarrier::complete_tx::bytes "
                    "[%0], [%1], %2, [%3];"
                    :: "r"(dst), "l"(src), "r"(2048u), "r"(mbar) : "memory");
            }
        }

        const int w   = tid >> 5;      // 8 warps
        const int lb  = tid & 31;      // lane = batch
        const int dir = w >> 2;        // 0 fwd / 1 bwd
        const int hl  = w & 3;         // local h
        const int h   = h_base + hl;

        // Bias sums (warp-uniform; c=0 => bx + bh only). 3 gates x 1 h.
        const float* bx = dir ? bxb : bxf;
        const float* bh = dir ? bhb : bhf;
        const float bi  = bx[h]       + bh[h];
        const float bgg = bx[512 + h] + bh[512 + h];
        const float bo  = bx[768 + h] + bh[768 + h];

        __syncthreads();      // xs ready
        mbar_wait0(mbar);     // W tile ready

        // GEMV: per k4: 1 x LDS.128 (CF, stride 132) + 3 broadcast W LDS.128
        // + 6 FMA2.
        unsigned int wrow[3];
        #pragma unroll
        for (int g = 0; g < 3; g++)
            wrow[g] = sb + SM_WSM + (((dir * 3 + g) * 4) + hl) * 512;

        const unsigned int xaddr = sb + SM_XS + (dir * 4224 + lb * 132) * 4;

        unsigned long long ai = 0ull, ag = 0ull, ao = 0ull;
        #pragma unroll 8
        for (int k4 = 0; k4 < 32; k4++) {
            unsigned long long xa, xb;
            lds_v2b64(xaddr + k4 * 16, xa, xb);
            unsigned long long w01, w23;
            lds_v2b64(wrow[0] + k4 * 16, w01, w23);
            ai = fma2(w01, xa, ai);
            ai = fma2(w23, xb, ai);
            lds_v2b64(wrow[1] + k4 * 16, w01, w23);
            ag = fma2(w01, xa, ag);
            ag = fma2(w23, xb, ag);
            lds_v2b64(wrow[2] + k4 * 16, w01, w23);
            ao = fma2(w01, xa, ao);
            ao = fma2(w23, xb, ao);
        }

        const float gi = acc_sum(ai) + bi;
        const float gg = acc_sum(ag) + bgg;
        const float go = acc_sum(ao) + bo;
        const float hyv = fsigm(go) * ftanh(fsigm(gi) * ftanh(gg));

        // Combine dirs via smem, store hy transposed.
        __syncthreads();
        if (dir == 1) red[hl * 33 + lb] = hyv;
        __syncthreads();
        if (dir == 0)
            g_hy[h * NB_B + b_base + lb] = hyv + red[hl * 33 + lb];

        __syncthreads();
        if (tid == 0) {
            __threadfence();
            atomicAdd(&g_wcnt[bg], 1u);
        }
    } else {
        // ================= HEAD (32 blocks, 4 batches each) =================
        const int hb = bid - 256;        // 0..31
        const int bg = hb >> 3;
        const int q  = hb & 7;
        const int b0 = bg * 32 + q * 4;

        float* Why_s = (float*)(dsm + SM_XS);      // [o*260 + k]  (CF LDS.128)
        float* hy_s  = (float*)(dsm + SMH_HYS);    // [bl*260 + k] (broadcast)
        float* red2  = (float*)(dsm + SMH_RED2);   // [bl*33 + o]

        // Stage Why during the worker phase.
        #pragma unroll
        for (int it = 0; it < 32; it++) {
            const int idx = tid + it * 256;      // 8192
            const int o = idx >> 8;
            const int k = idx & 255;
            Why_s[o * 260 + k] = Why[idx];
        }

        // Epoch-safe wait: N = hcnt/8 (this block hasn't incremented yet);
        // wait until wcnt >= 64*(N+1).
        if (tid == 0) {
            unsigned int h0;
            asm volatile("ld.global.relaxed.gpu.u32 %0, [%1];"
                         : "=r"(h0) : "l"(&g_hcnt[bg]));
            const unsigned int target = ((h0 >> 3) + 1u) * 64u;
            unsigned int v;
            do {
                asm volatile("ld.global.acquire.gpu.u32 %0, [%1];"
                             : "=r"(v) : "l"(&g_wcnt[bg]) : "memory");
                if ((int)(v - target) >= 0) break;
                __nanosleep(32);
            } while (true);
        }
        __syncthreads();

        // Stage hy for 4 batches (1024 floats) into padded rows.
        #pragma unroll
        for (int it = 0; it < 4; it++) {
            const int idx = tid + it * 256;
            const int bl  = idx & 3;
            const int k   = idx >> 2;
            hy_s[bl * 260 + k] = g_hy[k * NB_B + b0 + bl];
        }
        __syncthreads();

        // warp = (bl, k-half); lane = output o. 32 float4-iters:
        // 1 broadcast hy LDS.128 + 1 CF Why LDS.128 + 4 FMA.
        const int o  = tid & 31;
        const int w  = tid >> 5;
        const int bl = w & 3;
        const int kh = w >> 2;
        const float4* hy4 = (const float4*)(hy_s + bl * 260 + kh * 128);
        const float4* wy4 = (const float4*)(Why_s + o * 260 + kh * 128);

        float a0 = 0.f, a1 = 0.f, a2 = 0.f, a3 = 0.f;
        #pragma unroll 8
        for (int k4 = 0; k4 < 32; k4++) {
            const float4 hv = hy4[k4];
            const float4 wv = wy4[k4];
            a0 = fmaf(hv.x, wv.x, a0);
            a1 = fmaf(hv.y, wv.y, a1);
            a2 = fmaf(hv.z, wv.z, a2);
            a3 = fmaf(hv.w, wv.w, a3);
        }
        const float part = (a0 + a1) + (a2 + a3);

        if (kh == 1) red2[bl * 33 + o] = part;
        __syncthreads();
        if (kh == 0) {
            const float acc = part + red2[bl * 33 + o] + by[o];
            float mx = acc;
            #pragma unroll
            for (int off = 16; off; off >>= 1)
                mx = fmaxf(mx, __shfl_xor_sync(0xffffffffu, mx, off));
            float s = __expf(acc - mx);
            #pragma unroll
            for (int off = 16; off; off >>= 1)
                s += __shfl_xor_sync(0xffffffffu, s, off);
            out[(b0 + bl) * NB_OUT + o] = acc - mx - __logf(s);
        }

        __syncthreads();
        if (tid == 0) atomicAdd(&g_hcnt[bg], 1u);
    }
}

// Inputs in metadata order:
// 0 inputs(int32) 1 weight 2 Wxf 3 bxf 4 Whf(unused) 5 bhf
// 6 Wxb 7 bxb 8 Whb(unused) 9 bhb 10 Why 11 by
extern "C" void kernel_launch(void* const* d_in, const int* in_sizes, int n_in,
                              void* d_out, int out_size)
{
    const int*   inputs = (const int*)  d_in[0];
    const float* weight = (const float*)d_in[1];
    const float* Wxf    = (const float*)d_in[2];
    const float* bxf    = (const float*)d_in[3];
    const float* bhf    = (const float*)d_in[5];
    const float* Wxb    = (const float*)d_in[6];
    const float* bxb    = (const float*)d_in[7];
    const float* bhb    = (const float*)d_in[9];
    const float* Why    = (const float*)d_in[10];
    const float* by     = (const float*)d_in[11];
    float*       out    = (float*)d_out;

    static int configured = 0;
    if (!configured) {
        cudaFuncSetAttribute(bilstm_kernel,
                             cudaFuncAttributeMaxDynamicSharedMemorySize,
                             SMEM_BYTES);
        configured = 1;
    }

    bilstm_kernel<<<288, 256, SMEM_BYTES>>>(inputs, weight, Wxf, bxf, bhf,
                                            Wxb, bxb, bhb, Why, by, out);
}

// round 14
// speedup vs baseline: 1.2818x; 1.1272x over previous
#include <cuda_runtime.h>
#include <cstdint>

// Degenerate BiLSTM: h=c=0 => only emb[:,S-1] (fwd) and emb[:,0] (bwd) matter;
// f-gate dead; Whf/Whb unused.  B=128, S=2048, EMB=128, HID=256, OUT=32.
//
// R10 skeleton (measured best: 13.1us) + micro-shaves:
// Grid 160 = 128 workers (32 h-chunks x 4 batch-groups) + 32 head blocks.
// Worker: W tile via cp.async.bulk; x gathered 2-threads-per-row into 132-word
// padded rows (CF LDS.128); GEMV with fma.rn.f32x2, 2 h x 3 gates per warp;
// NO dir combine: fwd/bwd stored to separate g_hyA/g_hyB immediately (saves
// 2 syncs + smem round-trip); single sync + fence + wcnt release.
// Head (8 per bg, 4 batches each): stages Why[o][k] (260-pad) during worker
// phase; epoch-safe spin; staging adds hyA+hyB; vectorized float4 GEMV;
// 32-wide log-softmax.

#define NB_B   128
#define NB_S   2048
#define NB_EMB 128
#define NB_HID 256
#define NB_OUT 32

__device__ unsigned int g_wcnt[4];            // +32 per launch per bg (workers)
__device__ unsigned int g_hcnt[4];            // +8  per launch per bg (heads)
__device__ float        g_hyA[NB_HID * NB_B]; // fwd  [h][b]
__device__ float        g_hyB[NB_HID * NB_B]; // bwd  [h][b]

// dynamic smem byte offsets (worker / head overlays)
#define SM_XS    0              // worker: xs 8448 fl | head: Why_s 8320 fl
#define SM_WSM   33792          // worker: W 24576 B  | head: hy_s 4*260 fl
#define SM_RED2  37952          // head: red2 4*33 floats (528 B)
#define SM_MBAR  59424          // 8 B
#define SMEM_BYTES 59456

__device__ __forceinline__ float fsigm(float x) {
    return __fdividef(1.0f, 1.0f + __expf(-x));
}
__device__ __forceinline__ float ftanh(float x) {
    float r; asm("tanh.approx.f32 %0, %1;" : "=f"(r) : "f"(x)); return r;
}
__device__ __forceinline__ unsigned int smem_u32(const void* p) {
    unsigned int a;
    asm("{ .reg .u64 t; cvta.to.shared.u64 t, %1; cvt.u32.u64 %0, t; }"
        : "=r"(a) : "l"(p));
    return a;
}
__device__ __forceinline__ unsigned long long fma2(
    unsigned long long a, unsigned long long b, unsigned long long c) {
    unsigned long long d;
    asm("fma.rn.f32x2 %0, %1, %2, %3;" : "=l"(d) : "l"(a), "l"(b), "l"(c));
    return d;
}
__device__ __forceinline__ void lds_v2b64(unsigned int a,
                                          unsigned long long& x,
                                          unsigned long long& y) {
    asm volatile("ld.shared.v2.b64 {%0, %1}, [%2];" : "=l"(x), "=l"(y) : "r"(a));
}
__device__ __forceinline__ float acc_sum(unsigned long long v) {
    return __uint_as_float((unsigned int)v) + __uint_as_float((unsigned int)(v >> 32));
}
__device__ __forceinline__ void mbar_wait0(unsigned int mbar) {
    unsigned int done;
    asm volatile(
        "{\n\t.reg .pred p;\n\t"
        "mbarrier.try_wait.parity.acquire.cta.shared::cta.b64 p, [%1], 0;\n\t"
        "selp.b32 %0, 1, 0, p;\n\t}"
        : "=r"(done) : "r"(mbar) : "memory");
    if (!done) {
        asm volatile(
            "{\n\t.reg .pred P1;\n\t"
            "WL_%=:\n\t"
            "mbarrier.try_wait.parity.acquire.cta.shared::cta.b64 P1, [%0], 0, 0x989680;\n\t"
            "@P1 bra.uni WD_%=;\n\t"
            "bra.uni WL_%=;\n\t"
            "WD_%=:\n\t}"
            :: "r"(mbar) : "memory");
    }
}

__global__ void __launch_bounds__(256, 1) bilstm_kernel(
    const int*   __restrict__ inputs,   // [B, S]
    const float* __restrict__ weight,   // [VOCAB, EMB]
    const float* __restrict__ Wxf,      // [1024, 128]
    const float* __restrict__ bxf,
    const float* __restrict__ bhf,
    const float* __restrict__ Wxb,
    const float* __restrict__ bxb,
    const float* __restrict__ bhb,
    const float* __restrict__ Why,      // [32, 256]
    const float* __restrict__ by,       // [32]
    float*       __restrict__ out)      // [B, 32]
{
    extern __shared__ char dsm[];
    const int tid = threadIdx.x;
    const int bid = blockIdx.x;

    if (bid < 128) {
        // ================= WORKER =================
        const int hc     = bid & 31;
        const int bg     = bid >> 5;
        const int h_base = hc * 8;
        const int b_base = bg * 32;

        float* xs = (float*)(dsm + SM_XS);     // [dir*4224 + lb*132 + e]
        const unsigned int sb   = smem_u32(dsm);
        const unsigned int mbar = sb + SM_MBAR;

        // --- parallel staging ---
        if (tid < 128) {
            // 2 threads per (dir,lb) row; each copies 64 floats (16 float4).
            const int row  = tid >> 1;
            const int half = tid & 1;
            const int dir  = row >> 5;
            const int lb   = row & 31;
            const int tok  = inputs[(b_base + lb) * NB_S + (dir ? 0 : (NB_S - 1))];
            const float4* src = (const float4*)(weight + tok * NB_EMB + half * 64);
            float* dst = xs + dir * 4224 + lb * 132 + half * 64;
            #pragma unroll
            for (int e4 = 0; e4 < 16; e4++)
                *(float4*)(dst + e4 * 4) = src[e4];
        } else if (tid == 128) {
            asm volatile("mbarrier.init.shared.b64 [%0], 1;" :: "r"(mbar) : "memory");
            asm volatile("mbarrier.arrive.expect_tx.shared.b64 _, [%0], %1;"
                         :: "r"(mbar), "r"(24576u) : "memory");
            const int goff[3] = {0, 512, 768};
            #pragma unroll
            for (int c = 0; c < 6; c++) {
                const float* src = (c >= 3 ? Wxb : Wxf)
                                 + (goff[c % 3] + h_base) * NB_EMB;
                const unsigned int dst = sb + SM_WSM + c * 4096;
                asm volatile(
                    "cp.async.bulk.shared::cluster.global.mbarrier::complete_tx::bytes "
                    "[%0], [%1], %2, [%3];"
                    :: "r"(dst), "l"(src), "r"(4096u), "r"(mbar) : "memory");
            }
        }

        const int w   = tid >> 5;      // 8 warps
        const int lb  = tid & 31;      // lane = batch
        const int dir = w >> 2;        // 0 fwd / 1 bwd
        const int hp  = w & 3;         // h-pair

        // Bias sums (warp-uniform; c=0 => bx + bh only). 3 gates x 2 h.
        const float* bx = dir ? bxb : bxf;
        const float* bh = dir ? bhb : bhf;
        float bias[6];
        #pragma unroll
        for (int g = 0; g < 3; g++) {
            const int go = (g == 0 ? 0 : (g == 1 ? 512 : 768));
            #pragma unroll
            for (int j = 0; j < 2; j++) {
                const int h = h_base + 2 * hp + j;
                bias[g * 2 + j] = bx[go + h] + bh[go + h];
            }
        }

        __syncthreads();      // xs ready
        mbar_wait0(mbar);     // W tile ready

        // GEMV: per k4: 1 x LDS.128 (CF, stride 132) + 6 broadcast W LDS.128
        // + 12 FMA2.
        unsigned int wrow[6];
        #pragma unroll
        for (int g = 0; g < 3; g++)
            #pragma unroll
            for (int j = 0; j < 2; j++)
                wrow[g * 2 + j] = sb + SM_WSM
                                + (((dir * 3 + g) * 8) + 2 * hp + j) * 512;

        const unsigned int xaddr = sb + SM_XS + (dir * 4224 + lb * 132) * 4;

        unsigned long long acc[6] = {0ull, 0ull, 0ull, 0ull, 0ull, 0ull};
        #pragma unroll 8
        for (int k4 = 0; k4 < 32; k4++) {
            unsigned long long xa, xb;
            lds_v2b64(xaddr + k4 * 16, xa, xb);
            #pragma unroll
            for (int r = 0; r < 6; r++) {
                unsigned long long w01, w23;
                lds_v2b64(wrow[r] + k4 * 16, w01, w23);
                acc[r] = fma2(w01, xa, acc[r]);
                acc[r] = fma2(w23, xb, acc[r]);
            }
        }

        // Store each dir's hy immediately (no combine, no extra syncs).
        float* g_hy = dir ? g_hyB : g_hyA;
        #pragma unroll
        for (int j = 0; j < 2; j++) {
            const float gi = acc_sum(acc[0 * 2 + j]) + bias[0 * 2 + j];
            const float gg = acc_sum(acc[1 * 2 + j]) + bias[1 * 2 + j];
            const float go = acc_sum(acc[2 * 2 + j]) + bias[2 * 2 + j];
            const float hyv = fsigm(go) * ftanh(fsigm(gi) * ftanh(gg));
            g_hy[(h_base + 2 * hp + j) * NB_B + b_base + lb] = hyv;
        }

        __syncthreads();      // all warps' stores issued
        if (tid == 0) {
            __threadfence();
            atomicAdd(&g_wcnt[bg], 1u);
        }
    } else {
        // ================= HEAD (32 blocks, 4 batches each) =================
        const int hb = bid - 128;        // 0..31
        const int bg = hb >> 3;
        const int q  = hb & 7;
        const int b0 = bg * 32 + q * 4;

        float* Why_s = (float*)(dsm + SM_XS);    // [o*260 + k]  (CF LDS.128)
        float* hy_s  = (float*)(dsm + SM_WSM);   // [bl*260 + k] (broadcast)
        float* red2  = (float*)(dsm + SM_RED2);  // [bl*33 + o]

        // Hoist by (off the post-poll critical path).
        const float by_r = by[tid & 31];

        // Stage Why during the worker phase.
        #pragma unroll
        for (int it = 0; it < 32; it++) {
            const int idx = tid + it * 256;      // 8192
            const int o = idx >> 8;
            const int k = idx & 255;
            Why_s[o * 260 + k] = Why[idx];
        }

        // Epoch-safe wait: N = hcnt/8 (this block hasn't incremented yet);
        // wait until wcnt >= 32*(N+1).
        if (tid == 0) {
            unsigned int h0;
            asm volatile("ld.global.relaxed.gpu.u32 %0, [%1];"
                         : "=r"(h0) : "l"(&g_hcnt[bg]));
            const unsigned int target = ((h0 >> 3) + 1u) * 32u;
            unsigned int v;
            do {
                asm volatile("ld.global.acquire.gpu.u32 %0, [%1];"
                             : "=r"(v) : "l"(&g_wcnt[bg]) : "memory");
                if ((int)(v - target) >= 0) break;
                __nanosleep(16);
            } while (true);
        }
        __syncthreads();

        // Stage hy for 4 batches (1024 floats): add the two dir buffers.
        #pragma unroll
        for (int it = 0; it < 4; it++) {
            const int idx = tid + it * 256;
            const int bl  = idx & 3;
            const int k   = idx >> 2;
            const int g   = k * NB_B + b0 + bl;
            hy_s[bl * 260 + k] = __ldcg(&g_hyA[g]) + __ldcg(&g_hyB[g]);
        }
        __syncthreads();

        // warp = (bl, k-half); lane = output o. 32 float4-iters:
        // 1 broadcast hy LDS.128 + 1 CF Why LDS.128 + 4 FMA.
        const int o  = tid & 31;
        const int w  = tid >> 5;
        const int bl = w & 3;
        const int kh = w >> 2;
        const float4* hy4 = (const float4*)(hy_s + bl * 260 + kh * 128);
        const float4* wy4 = (const float4*)(Why_s + o * 260 + kh * 128);

        float a0 = 0.f, a1 = 0.f, a2 = 0.f, a3 = 0.f;
        #pragma unroll 8
        for (int k4 = 0; k4 < 32; k4++) {
            const float4 hv = hy4[k4];
            const float4 wv = wy4[k4];
            a0 = fmaf(hv.x, wv.x, a0);
            a1 = fmaf(hv.y, wv.y, a1);
            a2 = fmaf(hv.z, wv.z, a2);
            a3 = fmaf(hv.w, wv.w, a3);
        }
        const float part = (a0 + a1) + (a2 + a3);

        if (kh == 1) red2[bl * 33 + o] = part;
        __syncthreads();
        if (kh == 0) {
            const float acc = part + red2[bl * 33 + o] + by_r;
            float mx = acc;
            #pragma unroll
            for (int off = 16; off; off >>= 1)
                mx = fmaxf(mx, __shfl_xor_sync(0xffffffffu, mx, off));
            float s = __expf(acc - mx);
            #pragma unroll
            for (int off = 16; off; off >>= 1)
                s += __shfl_xor_sync(0xffffffffu, s, off);
            out[(b0 + bl) * NB_OUT + o] = acc - mx - __logf(s);
        }

        __syncthreads();
        if (tid == 0) atomicAdd(&g_hcnt[bg], 1u);
    }
}

// Inputs in metadata order:
// 0 inputs(int32) 1 weight 2 Wxf 3 bxf 4 Whf(unused) 5 bhf
// 6 Wxb 7 bxb 8 Whb(unused) 9 bhb 10 Why 11 by
extern "C" void kernel_launch(void* const* d_in, const int* in_sizes, int n_in,
                              void* d_out, int out_size)
{
    const int*   inputs = (const int*)  d_in[0];
    const float* weight = (const float*)d_in[1];
    const float* Wxf    = (const float*)d_in[2];
    const float* bxf    = (const float*)d_in[3];
    const float* bhf    = (const float*)d_in[5];
    const float* Wxb    = (const float*)d_in[6];
    const float* bxb    = (const float*)d_in[7];
    const float* bhb    = (const float*)d_in[9];
    const float* Why    = (const float*)d_in[10];
    const float* by     = (const float*)d_in[11];
    float*       out    = (float*)d_out;

    static int configured = 0;
    if (!configured) {
        cudaFuncSetAttribute(bilstm_kernel,
                             cudaFuncAttributeMaxDynamicSharedMemorySize,
                             SMEM_BYTES);
        configured = 1;
    }

    bilstm_kernel<<<160, 256, SMEM_BYTES>>>(inputs, weight, Wxf, bxf, bhf,
                                            Wxb, bxb, bhb, Why, by, out);
}